// round 4
// baseline (speedup 1.0000x reference)
#include <cuda_runtime.h>
#include <math.h>

#define Hd 128
#define Wd 128
#define Bn 4
#define HW (Hd*Wd)

// ---------------- scratch (device globals: no allocation allowed) ----------------
__device__ float g_offm[(size_t)Bn*8*27*HW];   // [b*8+g][27][h][w]  offsets(18) + sigmoid mask(9)
__device__ float g_target[(size_t)Bn*64*HW];   // deform output
__device__ float g_mid[(size_t)Bn*64*HW];      // conv1 output

// =====================================================================
// Kernel 1: per-group 3x3 conv producing 18 offset + 9 mask channels.
// grid (32 tiles, 32 bg), block 256. tile 32(w) x 16(h), 2 px/thread.
// =====================================================================
__global__ __launch_bounds__(256) void offset_kernel(
    const float* __restrict__ o_in, const float* __restrict__ pw,
    const float* __restrict__ pb,   const float* __restrict__ mw,
    const float* __restrict__ mb)
{
    __shared__ __align__(16) float tile[2][18*36];
    __shared__ __align__(16) float wsm[2][9*28];   // [tap][k] padded to 28

    const int t  = threadIdx.x;
    const int bg = blockIdx.y;
    const int b  = bg >> 3, g = bg & 7;
    const int tx = (blockIdx.x & 3) * 32;
    const int ty = (blockIdx.x >> 2) * 16;
    const int cg = t & 15, row = t >> 4;

    float acc0[28], acc1[28];
#pragma unroll
    for (int k = 0; k < 28; k++) { acc0[k] = 0.f; acc1[k] = 0.f; }

    const float* fbase = o_in + (size_t)(b*64 + g*8) * HW;

    float r_in[3]; float r_w = 0.f;
    auto fetch = [&](int ic) {
        const float* src = fbase + ic * HW;
#pragma unroll
        for (int k = 0; k < 3; k++) {
            int idx = t + k * 256;
            float v = 0.f;
            if (idx < 612) {
                int rr = idx / 34, cc = idx - rr * 34;
                int y = ty - 1 + rr, x = tx - 1 + cc;
                if (y >= 0 && y < Hd && x >= 0 && x < Wd) v = __ldg(&src[y*Wd + x]);
            }
            r_in[k] = v;
        }
        if (t < 243) {
            int kk = t / 9, tap = t - kk * 9;
            r_w = (kk < 18) ? __ldg(&pw[((g*18 + kk)*8 + ic)*9 + tap])
                            : __ldg(&mw[((g*9 + (kk-18))*8 + ic)*9 + tap]);
        }
    };

    fetch(0);
    int buf = 0;
    for (int ic = 0; ic < 8; ic++) {
#pragma unroll
        for (int k = 0; k < 3; k++) {
            int idx = t + k * 256;
            if (idx < 612) { int rr = idx / 34, cc = idx - rr * 34; tile[buf][rr*36 + cc] = r_in[k]; }
        }
        if (t < 243) { int kk = t / 9, tap = t - kk * 9; wsm[buf][tap*28 + kk] = r_w; }
        else if (t < 252) { wsm[buf][(t - 243)*28 + 27] = 0.f; }
        __syncthreads();
        if (ic + 1 < 8) fetch(ic + 1);

#pragma unroll
        for (int r = 0; r < 3; r++) {
            int base = (row + r)*36 + cg*2;
            float vv[4] = { tile[buf][base], tile[buf][base+1], tile[buf][base+2], tile[buf][base+3] };
#pragma unroll
            for (int s = 0; s < 3; s++) {
                const float4* wp = (const float4*)&wsm[buf][(r*3 + s)*28];
                float a = vv[s], bb = vv[s+1];
#pragma unroll
                for (int k4 = 0; k4 < 7; k4++) {
                    float4 w = wp[k4];
                    acc0[k4*4+0] += a*w.x; acc0[k4*4+1] += a*w.y;
                    acc0[k4*4+2] += a*w.z; acc0[k4*4+3] += a*w.w;
                    acc1[k4*4+0] += bb*w.x; acc1[k4*4+1] += bb*w.y;
                    acc1[k4*4+2] += bb*w.z; acc1[k4*4+3] += bb*w.w;
                }
            }
        }
        buf ^= 1;
    }

    const int y = ty + row, x = tx + cg*2;
    const size_t outb = (size_t)bg*27*HW + (size_t)y*Wd + x;
#pragma unroll
    for (int k = 0; k < 18; k++) {
        float bv = __ldg(&pb[g*18 + k]);
        float2 v = { acc0[k] + bv, acc1[k] + bv };
        *(float2*)&g_offm[outb + (size_t)k*HW] = v;
    }
#pragma unroll
    for (int k = 0; k < 9; k++) {
        float bv = __ldg(&mb[g*9 + k]);
        float a0 = acc0[18 + k] + bv, a1 = acc1[18 + k] + bv;
        float2 v = { 1.f/(1.f + expf(-a0)), 1.f/(1.f + expf(-a1)) };
        *(float2*)&g_offm[outb + (size_t)(18 + k)*HW] = v;
    }
}

// =====================================================================
// Kernel 2: deformable bilinear sampling + modulation + cw contraction.
// grid (64 tiles, 32 bg), block 256 = 16x16 pixels, 1 px/thread.
// =====================================================================
__global__ __launch_bounds__(256) void deform_kernel(
    const float* __restrict__ anchor, const float* __restrict__ cw)
{
    __shared__ __align__(16) float cwsm[576];  // [(c*9+n)*8 + oc]
    const int t  = threadIdx.x;
    const int bg = blockIdx.y;
    const int b  = bg >> 3, g = bg & 7;
    const int tx = (blockIdx.x & 7) * 16, ty = (blockIdx.x >> 3) * 16;

    for (int idx = t; idx < 576; idx += 256) {
        int oc = idx & 7; int cn = idx >> 3; int c = cn / 9, n = cn - c*9;
        cwsm[idx] = __ldg(&cw[((g*8 + oc)*8 + c)*9 + n]);
    }
    __syncthreads();

    const int jl = t & 15, il = t >> 4;
    const int i = ty + il, j = tx + jl;
    const float* offb = g_offm + (size_t)bg*27*HW + (size_t)i*Wd + j;
    const float* xb   = anchor + (size_t)(b*64 + g*8) * HW;

    float acc[8];
#pragma unroll
    for (int oc = 0; oc < 8; oc++) acc[oc] = 0.f;

#pragma unroll
    for (int n = 0; n < 9; n++) {
        float px = (float)(i + n/3) + __ldg(&offb[(size_t)n*HW]);        // i+1 + (n/3 - 1)
        float py = (float)(j + n%3) + __ldg(&offb[(size_t)(9 + n)*HW]);  // j+1 + (n%3 - 1)
        float mm = __ldg(&offb[(size_t)(18 + n)*HW]);
        float fx = floorf(px), fy = floorf(py);
        float x0 = fminf(fmaxf(fx,       0.f), 127.f);
        float x1 = fminf(fmaxf(fx + 1.f, 0.f), 127.f);
        float y0 = fminf(fmaxf(fy,       0.f), 127.f);
        float y1 = fminf(fmaxf(fy + 1.f, 0.f), 127.f);
        float pxc = fminf(fmaxf(px, 0.f), 127.f);
        float pyc = fminf(fmaxf(py, 0.f), 127.f);
        float gx0 = 1.f + (x0 - pxc);
        float gx1 = 1.f - (x1 - pxc);
        float gy0 = 1.f + (y0 - pyc);
        float gy1 = 1.f - (y1 - pyc);
        float glt = gx0*gy0*mm, grb = gx1*gy1*mm, glb = gx0*gy1*mm, grt = gx1*gy0*mm;
        int ix0 = (int)x0 * Wd, ix1 = (int)x1 * Wd;
        int iy0 = (int)y0,       iy1 = (int)y1;
#pragma unroll
        for (int c = 0; c < 8; c++) {
            const float* pl = xb + (size_t)c*HW;
            float v = glt*__ldg(&pl[ix0 + iy0]) + grb*__ldg(&pl[ix1 + iy1])
                    + glb*__ldg(&pl[ix0 + iy1]) + grt*__ldg(&pl[ix1 + iy0]);
            const float4* wp = (const float4*)&cwsm[(c*9 + n)*8];
            float4 w0 = wp[0], w1 = wp[1];
            acc[0] += v*w0.x; acc[1] += v*w0.y; acc[2] += v*w0.z; acc[3] += v*w0.w;
            acc[4] += v*w1.x; acc[5] += v*w1.y; acc[6] += v*w1.z; acc[7] += v*w1.w;
        }
    }

    const size_t ob = (size_t)(b*64 + g*8)*HW + (size_t)i*Wd + j;
#pragma unroll
    for (int oc = 0; oc < 8; oc++) g_target[ob + (size_t)oc*HW] = acc[oc];
}

// =====================================================================
// Kernels 3/4: direct 3x3 conv, 32x32 spatial tile, 16 oc x 4 px per thread.
// Double-buffered smem input (stride 36 for aligned LDS.128) + transposed weights.
// =====================================================================
template<int CIN, bool CONCAT, bool RESID>
__device__ __forceinline__ void conv_body(
    const float* __restrict__ inA, const float* __restrict__ inB,
    const float* __restrict__ wgt, const float* __restrict__ bias,
    const float* __restrict__ resid, float* __restrict__ out)
{
    __shared__ __align__(16) float tile[2][34*36];
    __shared__ __align__(16) float wsm[2][9*16];   // [tap][oc]

    const int t  = threadIdx.x;
    const int tx = (blockIdx.x & 3) * 32, ty = (blockIdx.x >> 2) * 32;
    const int ocb = blockIdx.y * 16;
    const int b   = blockIdx.z;
    const int cg = t & 7, row = t >> 3;
    const int col0 = cg * 4;

    float acc[4][16];
#pragma unroll
    for (int p = 0; p < 4; p++)
#pragma unroll
        for (int o = 0; o < 16; o++) acc[p][o] = 0.f;

    float r_in[5]; float r_w = 0.f;
    auto fetch = [&](int ic) {
        const float* src;
        if (CONCAT) src = (ic < 64) ? (inA + (size_t)(b*64 + ic)*HW)
                                    : (inB + (size_t)(b*64 + ic - 64)*HW);
        else        src = inA + (size_t)(b*CIN + ic)*HW;
#pragma unroll
        for (int k = 0; k < 5; k++) {
            int idx = t + k * 256;
            float v = 0.f;
            if (idx < 1156) {
                int rr = idx / 34, cc = idx - rr * 34;
                int y = ty - 1 + rr, x = tx - 1 + cc;
                if (y >= 0 && y < Hd && x >= 0 && x < Wd) v = __ldg(&src[y*Wd + x]);
            }
            r_in[k] = v;
        }
        if (t < 144) {
            int o = t / 9, tap = t - o * 9;
            r_w = __ldg(&wgt[((size_t)(ocb + o)*CIN + ic)*9 + tap]);
        }
    };

    fetch(0);
    int buf = 0;
    for (int ic = 0; ic < CIN; ic++) {
#pragma unroll
        for (int k = 0; k < 5; k++) {
            int idx = t + k * 256;
            if (idx < 1156) { int rr = idx / 34, cc = idx - rr * 34; tile[buf][rr*36 + cc] = r_in[k]; }
        }
        if (t < 144) { int o = t / 9, tap = t - o * 9; wsm[buf][tap*16 + o] = r_w; }
        __syncthreads();
        if (ic + 1 < CIN) fetch(ic + 1);

#pragma unroll
        for (int r = 0; r < 3; r++) {
            const float* trow = &tile[buf][(row + r)*36 + col0];
            float4 v4 = *(const float4*)trow;
            float v[6] = { v4.x, v4.y, v4.z, v4.w, trow[4], trow[5] };
#pragma unroll
            for (int s = 0; s < 3; s++) {
                const float4* wp = (const float4*)&wsm[buf][(r*3 + s)*16];
#pragma unroll
                for (int o4 = 0; o4 < 4; o4++) {
                    float4 w = wp[o4];
#pragma unroll
                    for (int p = 0; p < 4; p++) {
                        float vv = v[p + s];
                        acc[p][o4*4+0] += vv*w.x; acc[p][o4*4+1] += vv*w.y;
                        acc[p][o4*4+2] += vv*w.z; acc[p][o4*4+3] += vv*w.w;
                    }
                }
            }
        }
        buf ^= 1;
    }

    const int y = ty + row, x = tx + col0;
#pragma unroll
    for (int o = 0; o < 16; o++) {
        float bv = __ldg(&bias[ocb + o]);
        size_t oidx = ((size_t)(b*64 + ocb + o)*Hd + y)*Wd + x;
        float4 v = { acc[0][o] + bv, acc[1][o] + bv, acc[2][o] + bv, acc[3][o] + bv };
        if (RESID) {
            float4 rr = *(const float4*)&resid[oidx];
            v.x += rr.x; v.y += rr.y; v.z += rr.z; v.w += rr.w;
        }
        *(float4*)&out[oidx] = v;
    }
}

__global__ __launch_bounds__(256, 2) void conv1_kernel(
    const float* __restrict__ anchor, const float* __restrict__ w1,
    const float* __restrict__ b1)
{
    conv_body<128, true, false>(g_target, anchor, w1, b1, nullptr, g_mid);
}

__global__ __launch_bounds__(256, 2) void conv2_kernel(
    const float* __restrict__ w2, const float* __restrict__ b2,
    float* __restrict__ out)
{
    conv_body<64, false, true>(g_mid, nullptr, w2, b2, g_target, out);
}

// =====================================================================
extern "C" void kernel_launch(void* const* d_in, const int* in_sizes, int n_in,
                              void* d_out, int out_size)
{
    const float* o      = (const float*)d_in[0];
    const float* anchor = (const float*)d_in[1];
    const float* pw     = (const float*)d_in[2];
    const float* pb     = (const float*)d_in[3];
    const float* mw     = (const float*)d_in[4];
    const float* mb     = (const float*)d_in[5];
    const float* cw     = (const float*)d_in[6];
    const float* w1     = (const float*)d_in[7];
    const float* b1     = (const float*)d_in[8];
    const float* w2     = (const float*)d_in[9];
    const float* b2     = (const float*)d_in[10];
    float* out = (float*)d_out;

    offset_kernel<<<dim3(32, 32), 256>>>(o, pw, pb, mw, mb);
    deform_kernel<<<dim3(64, 32), 256>>>(anchor, cw);
    conv1_kernel <<<dim3(16, 4, 4), 256>>>(anchor, w1, b1);
    conv2_kernel <<<dim3(16, 4, 4), 256>>>(w2, b2, out);
}